// round 13
// baseline (speedup 1.0000x reference)
#include <cuda_runtime.h>
#include <cuda_bf16.h>
#include <cstdint>

// Problem constants (fixed shapes)
#define BT    16384      // B*T
#define HID   512
#define NP    30
#define NU    600
#define NA    80
#define NK    10

__device__ __forceinline__ uint32_t smem_u32(const void* p) {
    return (uint32_t)__cvta_generic_to_shared(p);
}
__device__ __forceinline__ void ldsm_x4(uint32_t& r0, uint32_t& r1,
                                        uint32_t& r2, uint32_t& r3, uint32_t addr) {
    asm volatile("ldmatrix.sync.aligned.m8n8.x4.shared.b16 {%0,%1,%2,%3}, [%4];"
                 : "=r"(r0), "=r"(r1), "=r"(r2), "=r"(r3) : "r"(addr));
}
__device__ __forceinline__ void mma_bf16(float* c, const uint32_t* a,
                                         uint32_t b0, uint32_t b1) {
    asm volatile(
        "mma.sync.aligned.m16n8k16.row.col.f32.bf16.bf16.f32 "
        "{%0,%1,%2,%3}, {%4,%5,%6,%7}, {%8,%9}, {%0,%1,%2,%3};"
        : "+f"(c[0]), "+f"(c[1]), "+f"(c[2]), "+f"(c[3])
        : "r"(a[0]), "r"(a[1]), "r"(a[2]), "r"(a[3]), "r"(b0), "r"(b1));
}

// ---------------------------------------------------------------------------
// SINGLE fused kernel. 256 CTAs x 64 bt rows, 256 threads (8 warps).
//  Prologue: A chunk-0 LDGs issued FIRST; then each CTA converts full W
//            (read LINEARLY, coalesced float4) -> bf16 hi/lo smem
//            [32 n][520 k] (k-linear, 1040B row stride = LDSM-clean).
//  Phase A:  HMMA GEMM M=64 N=32(pad) K=512, 8 chunks of 64, DOUBLE-BUFFERED
//            A tiles -> ONE sync per chunk. 3-term bf16 split
//            (Ah*Wh + Ah*Wl + Al*Wh; missing term ~2^-17).
//  Phase B:  window for same 64 bt (phi once per (bt,u), charseq rows [0,32)
//            staged, analytic cutoff + global tail). scs/sphi alias W region.
// ---------------------------------------------------------------------------
#define K1T    256
#define MROWS  64
#define CHUNK  64
#define NCH    (HID / CHUNK)   // 8
#define ASTR   72              // A smem row stride (bf16): 144B, LDSM-clean
#define WSTR   520             // W smem row stride (bf16): 1040B, LDSM-clean

#define OFF_WH   0              // 32*520*2 = 33280
#define OFF_WL   33280          // 33280            (-> 66560)
#define OFF_A    66560          // 4 x 9216: [buf0 hi][buf0 lo][buf1 hi][buf1 lo]
#define ABUF     9216
#define OFF_SPAR 103424         // 30*64*4 = 7680
#define OFF_CUT  111104         // 64*4    = 256
#define SMEM_TOT 111360
#define OFF_SCS  0              // 32*80*4 = 10240 (aliases W after GEMM)
#define OFF_SPHI 10240          // 64*33*4 = 8448  (aliases W after GEMM)

__global__ __launch_bounds__(K1T) void k_fused(
    const float* __restrict__ lstm,
    const float* __restrict__ W,
    const float* __restrict__ bias,
    const float* __restrict__ charseq,
    float* __restrict__ out)
{
    extern __shared__ __align__(16) char buf[];
    __nv_bfloat16* sWh = reinterpret_cast<__nv_bfloat16*>(buf + OFF_WH);
    __nv_bfloat16* sWl = reinterpret_cast<__nv_bfloat16*>(buf + OFF_WL);
    float*         spar = reinterpret_cast<float*>(buf + OFF_SPAR);  // [p][bl]

    const int tid = threadIdx.x;
    const int wid = tid >> 5;
    const int lid = tid & 31;
    const int t0  = blockIdx.x * MROWS;
    const int m0    = (wid >> 1) * 16;
    const int nhalf = (wid & 1) * 16;
    const uint32_t sbase = smem_u32(buf);

    // ---- A chunk-0 prefetch FIRST (latency overlapped by W convert below)
    float4 va[4];
    #pragma unroll
    for (int j = 0; j < 4; j++) {
        int idx = tid + K1T * j;          // 0..1023
        int row = idx >> 4, c4 = idx & 15;
        va[j] = *reinterpret_cast<const float4*>(
            lstm + (size_t)(t0 + row) * HID + c4 * 4);
    }

    // ---- W -> bf16 hi/lo smem, COALESCED linear read (15 float4 / thread)
    {
        const float4* w4 = reinterpret_cast<const float4*>(W);
        #pragma unroll
        for (int j = 0; j < 15; j++) {
            int i4 = tid + K1T * j;       // 0..3839
            float4 v = w4[i4];
            float vals[4] = {v.x, v.y, v.z, v.w};
            int e0 = i4 * 4;
            #pragma unroll
            for (int s = 0; s < 4; s++) {
                int ee = e0 + s;
                int k  = ee / 30;
                int n  = ee - k * 30;
                float f = vals[s];
                __nv_bfloat16 hi = __float2bfloat16(f);
                __nv_bfloat16 lo = __float2bfloat16(f - __bfloat162float(hi));
                sWh[n * WSTR + k] = hi;
                sWl[n * WSTR + k] = lo;
            }
        }
        // zero pad rows n=30,31 (outputs discarded, but avoid garbage frags)
        #pragma unroll
        for (int j = 0; j < 4; j++) {
            int idx = tid + K1T * j;      // 0..1023
            int n = 30 + (idx & 1), k = idx >> 1;
            sWh[n * WSTR + k] = __float2bfloat16(0.f);
            sWl[n * WSTR + k] = __float2bfloat16(0.f);
        }
    }

    // ---- STS chunk 0 into A buf0
    auto sts_chunk = [&](const float4* v, int bsel) {
        __nv_bfloat16* dAh = reinterpret_cast<__nv_bfloat16*>(
            buf + OFF_A + bsel * 2 * ABUF);
        __nv_bfloat16* dAl = reinterpret_cast<__nv_bfloat16*>(
            buf + OFF_A + bsel * 2 * ABUF + ABUF);
        #pragma unroll
        for (int j = 0; j < 4; j++) {
            int idx = tid + K1T * j;
            int row = idx >> 4, c4 = idx & 15;
            float4 x = v[j];
            __nv_bfloat162 h01 = __float22bfloat162_rn(make_float2(x.x, x.y));
            __nv_bfloat162 h23 = __float22bfloat162_rn(make_float2(x.z, x.w));
            float2 f01 = __bfloat1622float2(h01);
            float2 f23 = __bfloat1622float2(h23);
            __nv_bfloat162 l01 = __float22bfloat162_rn(
                make_float2(x.x - f01.x, x.y - f01.y));
            __nv_bfloat162 l23 = __float22bfloat162_rn(
                make_float2(x.z - f23.x, x.w - f23.y));
            *reinterpret_cast<uint2*>(&dAh[row * ASTR + c4 * 4]) =
                make_uint2(*reinterpret_cast<uint32_t*>(&h01),
                           *reinterpret_cast<uint32_t*>(&h23));
            *reinterpret_cast<uint2*>(&dAl[row * ASTR + c4 * 4]) =
                make_uint2(*reinterpret_cast<uint32_t*>(&l01),
                           *reinterpret_cast<uint32_t*>(&l23));
        }
    };
    sts_chunk(va, 0);
    __syncthreads();

    // ======================= Phase A mainloop =======================
    float acc[2][4];
    #pragma unroll
    for (int n = 0; n < 2; n++)
        #pragma unroll
        for (int j = 0; j < 4; j++) acc[n][j] = 0.f;

    const uint32_t aoff = (uint32_t)((m0 + (lid & 15)) * ASTR +
                                     ((lid & 16) ? 8 : 0)) * 2;
    const int b_n = nhalf + (lid & 7) + ((lid & 16) ? 8 : 0);
    const uint32_t boffH = sbase + OFF_WH +
        (uint32_t)(b_n * WSTR + ((lid & 8) ? 8 : 0)) * 2;
    const uint32_t boffL = boffH + (OFF_WL - OFF_WH);

    #pragma unroll 2
    for (int ch = 0; ch < NCH; ch++) {
        // issue next chunk's LDGs early (covered by MMA below)
        if (ch + 1 < NCH) {
            int k0 = (ch + 1) * CHUNK;
            #pragma unroll
            for (int j = 0; j < 4; j++) {
                int idx = tid + K1T * j;
                int row = idx >> 4, c4 = idx & 15;
                va[j] = *reinterpret_cast<const float4*>(
                    lstm + (size_t)(t0 + row) * HID + k0 + c4 * 4);
            }
        }

        // MMA from buf[ch&1]
        const uint32_t aH = sbase + OFF_A + (uint32_t)((ch & 1) * 2 * ABUF) + aoff;
        const uint32_t aL = aH + ABUF;
        const uint32_t chb = (uint32_t)(ch * CHUNK) * 2;   // W k-offset bytes
        #pragma unroll
        for (int ks = 0; ks < 4; ks++) {
            uint32_t koff = (uint32_t)(ks * 16) * 2;
            uint32_t ah[4], al[4], bh[4], bl[4];
            ldsm_x4(ah[0], ah[1], ah[2], ah[3], aH + koff);
            ldsm_x4(al[0], al[1], al[2], al[3], aL + koff);
            ldsm_x4(bh[0], bh[1], bh[2], bh[3], boffH + chb + koff);
            ldsm_x4(bl[0], bl[1], bl[2], bl[3], boffL + chb + koff);
            mma_bf16(acc[0], ah, bh[0], bh[1]);
            mma_bf16(acc[0], ah, bl[0], bl[1]);
            mma_bf16(acc[0], al, bh[0], bh[1]);
            mma_bf16(acc[1], ah, bh[2], bh[3]);
            mma_bf16(acc[1], ah, bl[2], bl[3]);
            mma_bf16(acc[1], al, bh[2], bh[3]);
        }

        // stage next chunk into the other buffer; single barrier per chunk
        if (ch + 1 < NCH) sts_chunk(va, (ch + 1) & 1);
        __syncthreads();
    }

    // epilogue: +bias, exp, negate b-block, params -> spar[p][bl]
    {
        const int g  = lid >> 2;
        const int tg = lid & 3;
        #pragma unroll
        for (int nt = 0; nt < 2; nt++) {
            #pragma unroll
            for (int dp = 0; dp < 2; dp++) {
                int p = nhalf + nt * 8 + tg * 2 + dp;
                if (p < NP) {
                    float bz = bias[p];
                    float e0 = expf(acc[nt][dp] + bz);
                    float e1 = expf(acc[nt][2 + dp] + bz);
                    if (p >= NK && p < 2 * NK) { e0 = -e0; e1 = -e1; }
                    spar[p * MROWS + m0 + g]     = e0;
                    spar[p * MROWS + m0 + g + 8] = e1;
                }
            }
        }
    }
    __syncthreads();   // spar complete; W region now free for scs/sphi

    // ======================= Phase B: window =======================
    float* scs  = reinterpret_cast<float*>(buf + OFF_SCS);   // [32][80]
    float* sphi = reinterpret_cast<float*>(buf + OFF_SPHI);  // [64][33]
    int*   scut = reinterpret_cast<int*>(buf + OFF_CUT);     // [64]

    const int b = t0 >> 10;
    const float* cbase = charseq + (size_t)b * NU * NA;

    // stage charseq rows [0,32): 640 float4
    {
        const float4* cb4 = reinterpret_cast<const float4*>(cbase);
        float4* scs4 = reinterpret_cast<float4*>(scs);
        #pragma unroll
        for (int j = 0; j < 3; j++) {
            int idx = tid + K1T * j;
            if (idx < 32 * (NA / 4)) scs4[idx] = cb4[idx];
        }
    }

    // phi: thread (bl = tid>>2, q = tid&3) covers u = q + 4r, r < 8
    {
        const int bl = tid >> 2, q = tid & 3;
        float a[NK], nb[NK], kk[NK];
        #pragma unroll
        for (int k = 0; k < NK; k++) {
            a[k]  = spar[k * MROWS + bl];
            nb[k] = spar[(NK + k) * MROWS + bl];      // -b_k
            kk[k] = spar[(2 * NK + k) * MROWS + bl];
        }
        // u > kappa + sqrt(48/b): term < exp(-48) -> truncate
        float cut = 1.f;
        #pragma unroll
        for (int k = 0; k < NK; k++)
            cut = fmaxf(cut, kk[k] + __fsqrt_rn(__fdividef(48.f, -nb[k])));
        int ucut = min(NU, (int)cut + 1);
        if (q == 0) scut[bl] = ucut;
        #pragma unroll
        for (int r = 0; r < 8; r++) {
            int u = q + 4 * r;
            if (u < ucut) {
                float uf  = (float)u;
                float phi = 0.f;
                #pragma unroll
                for (int k = 0; k < NK; k++) {
                    float d = kk[k] - uf;
                    phi += a[k] * __expf(nb[k] * d * d);
                }
                sphi[bl * 33 + u] = phi;
            }
        }
    }
    __syncthreads();

    // accumulate: thread (bl = tid>>2, sub = tid&3) owns 20 a-cols
    {
        const int bl  = tid >> 2;
        const int sub = tid & 3;
        const int ucut = scut[bl];
        const int uend = min(ucut, 32);

        float acc2[20];
        #pragma unroll
        for (int j = 0; j < 20; j++) acc2[j] = 0.f;

        for (int u = 0; u < uend; u++) {
            float phi = sphi[bl * 33 + u];
            const float* r = scs + u * NA + sub * 20;
            #pragma unroll
            for (int j = 0; j < 5; j++) {
                float4 c = *reinterpret_cast<const float4*>(r + 4 * j);
                acc2[4 * j + 0] = fmaf(phi, c.x, acc2[4 * j + 0]);
                acc2[4 * j + 1] = fmaf(phi, c.y, acc2[4 * j + 1]);
                acc2[4 * j + 2] = fmaf(phi, c.z, acc2[4 * j + 2]);
                acc2[4 * j + 3] = fmaf(phi, c.w, acc2[4 * j + 3]);
            }
        }
        // tail u >= 32 (analytically unreachable; correctness fallback)
        if (ucut > 32) {
            float a[NK], nb[NK], kk[NK];
            #pragma unroll
            for (int k = 0; k < NK; k++) {
                a[k]  = spar[k * MROWS + bl];
                nb[k] = spar[(NK + k) * MROWS + bl];
                kk[k] = spar[(2 * NK + k) * MROWS + bl];
            }
            for (int u = 32; u < ucut; u++) {
                float uf  = (float)u;
                float phi = 0.f;
                #pragma unroll
                for (int k = 0; k < NK; k++) {
                    float d = kk[k] - uf;
                    phi += a[k] * __expf(nb[k] * d * d);
                }
                const float* r = cbase + (size_t)u * NA + sub * 20;
                #pragma unroll
                for (int j = 0; j < 20; j++)
                    acc2[j] = fmaf(phi, __ldg(r + j), acc2[j]);
            }
        }

        float4* op = reinterpret_cast<float4*>(
            out + (size_t)(t0 + bl) * NA + sub * 20);
        #pragma unroll
        for (int j = 0; j < 5; j++)
            op[j] = make_float4(acc2[4 * j], acc2[4 * j + 1],
                                acc2[4 * j + 2], acc2[4 * j + 3]);
    }
}

// ---------------------------------------------------------------------------
extern "C" void kernel_launch(void* const* d_in, const int* in_sizes, int n_in,
                              void* d_out, int out_size)
{
    const float* lstm = (const float*)d_in[0];   // [16,1024,512]
    const float* cs   = (const float*)d_in[1];   // [16,600,80]
    const float* W    = (const float*)d_in[2];   // [512,30]
    const float* bias = (const float*)d_in[3];   // [30]
    float* out = (float*)d_out;                  // [16,1024,80]

    (void)in_sizes; (void)n_in; (void)out_size;

    static int smem_set = 0;
    if (!smem_set) {
        cudaFuncSetAttribute(k_fused,
                             cudaFuncAttributeMaxDynamicSharedMemorySize,
                             SMEM_TOT);
        smem_set = 1;
    }
    k_fused<<<BT / MROWS, K1T, SMEM_TOT>>>(lstm, W, bias, cs, out);
}